// round 1
// baseline (speedup 1.0000x reference)
#include <cuda_runtime.h>
#include <cuda_bf16.h>
#include <math.h>

// Shapes: B=8, C=64 (concat of 2x32), H=W=64, HW=4096, D=C/2=32
#define BATCH 8
#define HW    4096
#define DHALF 32      // q/k/u/y channel dim
#define CFULL 64

// Scratch (device globals; no runtime allocation)
__device__ float g_q[BATCH * HW * DHALF];    // [b][n][32]
__device__ float g_k[BATCH * HW * DHALF];    // [b][m][32]
__device__ float g_u[BATCH * HW * DHALF];    // [b][m][32]  u = (Wsc@Wv)@x
__device__ float g_y[BATCH * HW * DHALF];    // [b][n][32]  y = Wsc@x
__device__ float g_zinv[BATCH * HW];         // gamma / Z[m]
__device__ float g_wu[DHALF * CFULL];        // Wsc@Wv

// ---------------------------------------------------------------------------
// K0: Wu = Wsc @ Wv   (32x64 = 32x64 @ 64x64)
// ---------------------------------------------------------------------------
__global__ __launch_bounds__(256) void k0_wu(const float* __restrict__ Wsc,
                                             const float* __restrict__ Wv) {
    int idx = blockIdx.x * 256 + threadIdx.x;
    if (idx < DHALF * CFULL) {
        int p = idx >> 6, c = idx & 63;
        float s = 0.f;
        #pragma unroll 8
        for (int t = 0; t < 64; t++) s = fmaf(Wsc[p * 64 + t], Wv[t * 64 + c], s);
        g_wu[idx] = s;
    }
}

// ---------------------------------------------------------------------------
// K1: projections. grid (HW/128, B), 256 threads.
//   q = Wq@x + bq ; k = Wk@x + bk ; u = Wu@x ; y = Wsc@x
// x[c][n] with c<32 -> x1, else x2. Outputs stored [n][32] row-major.
// ---------------------------------------------------------------------------
__global__ __launch_bounds__(256) void k1_proj(
    const float* __restrict__ x1, const float* __restrict__ x2,
    const float* __restrict__ Wq, const float* __restrict__ bq,
    const float* __restrict__ Wk, const float* __restrict__ bk,
    const float* __restrict__ Wsc) {
    __shared__ float xs[64 * 128];     // [c][px]
    __shared__ float wsm[64 * 32];     // [c][o] (transposed weights)

    int b = blockIdx.y;
    int n0 = blockIdx.x * 128;
    int t = threadIdx.x;

    // Load x tile: 64 ch x 128 px, vectorized, coalesced along n
    #pragma unroll
    for (int i = 0; i < 8; i++) {
        int idx = t + i * 256;            // float4 index, 2048 total
        int c = idx >> 5, pg = idx & 31;
        const float* src = (c < 32) ? (x1 + (size_t)(b * 32 + c) * HW)
                                    : (x2 + (size_t)(b * 32 + (c - 32)) * HW);
        float4 v = *(const float4*)(src + n0 + pg * 4);
        *(float4*)(xs + c * 128 + pg * 4) = v;
    }

    int d = t & 31;
    int pxb = (t >> 5) * 16;

    for (int p = 0; p < 4; p++) {
        const float* W = (p == 0) ? Wq : (p == 1) ? Wk : (p == 2) ? g_wu : Wsc;
        __syncthreads();   // protect wsm vs previous compute (also covers xs first time)
        #pragma unroll
        for (int i = 0; i < 8; i++) {
            int idx = t + i * 256;        // 2048 elems
            int o = idx >> 6, c = idx & 63;
            wsm[c * 32 + o] = W[idx];
        }
        __syncthreads();

        float bias = (p == 0) ? bq[d] : (p == 1) ? bk[d] : 0.f;
        float acc[16];
        #pragma unroll
        for (int j = 0; j < 16; j++) acc[j] = bias;

        for (int c = 0; c < 64; c++) {
            float wv = wsm[c * 32 + d];
            const float* xr = xs + c * 128 + pxb;
            #pragma unroll
            for (int j = 0; j < 16; j++) acc[j] = fmaf(wv, xr[j], acc[j]);
        }

        float* outp = (p == 0) ? g_q : (p == 1) ? g_k : (p == 2) ? g_u : g_y;
        float* dst = outp + ((size_t)b * HW + n0 + pxb) * DHALF + d;
        #pragma unroll
        for (int j = 0; j < 16; j++) dst[j * DHALF] = acc[j];
    }
}

// transposed smem tile load: src rows [row][32] -> dst [d][68]
__device__ __forceinline__ void load_tile_T(float* __restrict__ dst,
                                            const float* __restrict__ src, int t) {
    #pragma unroll
    for (int i = 0; i < 2; i++) {
        int idx = t + i * 256;            // 512 float4s (64 rows x 8)
        int row = idx >> 3, dg = idx & 7;
        float4 v = *(const float4*)(src + row * 32 + dg * 4);
        dst[(dg * 4 + 0) * 68 + row] = v.x;
        dst[(dg * 4 + 1) * 68 + row] = v.y;
        dst[(dg * 4 + 2) * 68 + row] = v.z;
        dst[(dg * 4 + 3) * 68 + row] = v.w;
    }
}

// ---------------------------------------------------------------------------
// K2: column stats. grid (HW/64, B), 256 threads. CTA owns 64 m-columns,
// streams all n computing Z[m] = sum_n exp(q[n]·k[m]); stores gamma/Z.
// No max-subtraction: |s| <= ~6 -> exp safe in fp32.
// ---------------------------------------------------------------------------
__global__ __launch_bounds__(256) void k2_stats(const float* __restrict__ gamma) {
    __shared__ float kt[32 * 68];
    __shared__ float qt[32 * 68];
    __shared__ float red[16 * 68];

    int b = blockIdx.y;
    int m0 = blockIdx.x * 64;
    int t = threadIdx.x;
    int tx = t & 15, ty = t >> 4;

    load_tile_T(kt, g_k + ((size_t)b * HW + m0) * DHALF, t);

    float zacc[4] = {0.f, 0.f, 0.f, 0.f};

    for (int nc = 0; nc < 64; nc++) {
        __syncthreads();
        load_tile_T(qt, g_q + ((size_t)b * HW + nc * 64) * DHALF, t);
        __syncthreads();

        float s[4][4];
        #pragma unroll
        for (int i = 0; i < 4; i++)
            #pragma unroll
            for (int j = 0; j < 4; j++) s[i][j] = 0.f;

        #pragma unroll 4
        for (int d = 0; d < 32; d++) {
            float4 qv = *(const float4*)(qt + d * 68 + ty * 4);
            float4 kv = *(const float4*)(kt + d * 68 + tx * 4);
            float q4[4] = {qv.x, qv.y, qv.z, qv.w};
            float k4[4] = {kv.x, kv.y, kv.z, kv.w};
            #pragma unroll
            for (int i = 0; i < 4; i++)
                #pragma unroll
                for (int j = 0; j < 4; j++) s[i][j] = fmaf(q4[i], k4[j], s[i][j]);
        }
        #pragma unroll
        for (int i = 0; i < 4; i++)
            #pragma unroll
            for (int j = 0; j < 4; j++) zacc[j] += __expf(s[i][j]);
    }

    __syncthreads();
    #pragma unroll
    for (int j = 0; j < 4; j++) red[ty * 68 + tx * 4 + j] = zacc[j];
    __syncthreads();

    if (t < 64) {
        float sum = 0.f;
        #pragma unroll
        for (int r = 0; r < 16; r++) sum += red[r * 68 + t];
        g_zinv[b * HW + m0 + t] = gamma[0] / sum;
    }
}

// ---------------------------------------------------------------------------
// K3: fused output. grid (HW/64, B), 256 threads. CTA owns 64 queries (n)
// x all 32 outputs (o). Loops over m in 64-chunks:
//   stage1: s = q·k, es[n][m] = exp(s)
//   stage2: acc[n][o] += es[n][m] * (gamma * u[o][m] / Z[m])
// epilogue: out[b][o][n] = y[o][n] + acc.
// ---------------------------------------------------------------------------
__global__ __launch_bounds__(256) void k3_out(float* __restrict__ out) {
    __shared__ float qt[32 * 68];      // q tile transposed [d][n]
    __shared__ float kt[32 * 68];      // k chunk transposed [d][m]
    __shared__ float es[64 * 68];      // exp(s) [n][m]
    __shared__ float ws[64 * 40];      // scaled u [m][o]

    int b = blockIdx.y;
    int n0 = blockIdx.x * 64;
    int t = threadIdx.x;
    int tx = t & 15, ty = t >> 4;      // stage1: 4n x 4m per thread
    int oid = t & 7, nid = t >> 3;     // stage2: 2n x 4o per thread

    load_tile_T(qt, g_q + ((size_t)b * HW + n0) * DHALF, t);

    float acc[2][4];
    #pragma unroll
    for (int r = 0; r < 2; r++)
        #pragma unroll
        for (int j = 0; j < 4; j++) acc[r][j] = 0.f;

    for (int mc = 0; mc < 64; mc++) {
        int m0 = mc * 64;
        __syncthreads();               // protect kt/ws/es vs previous stage2 reads
        load_tile_T(kt, g_k + ((size_t)b * HW + m0) * DHALF, t);

        const float* uin = g_u + ((size_t)b * HW + m0) * DHALF;
        const float* zin = g_zinv + b * HW + m0;
        #pragma unroll
        for (int i = 0; i < 2; i++) {
            int idx = t + i * 256;     // 512 float4s
            int row = idx >> 3, og = idx & 7;
            float4 v = *(const float4*)(uin + row * 32 + og * 4);
            float zi = zin[row];
            v.x *= zi; v.y *= zi; v.z *= zi; v.w *= zi;
            *(float4*)(ws + row * 40 + og * 4) = v;
        }
        __syncthreads();

        // stage1: s = q @ k^T for 4x4 block, write exp to es[n][m]
        float s[4][4];
        #pragma unroll
        for (int i = 0; i < 4; i++)
            #pragma unroll
            for (int j = 0; j < 4; j++) s[i][j] = 0.f;

        #pragma unroll 4
        for (int d = 0; d < 32; d++) {
            float4 qv = *(const float4*)(qt + d * 68 + ty * 4);
            float4 kv = *(const float4*)(kt + d * 68 + tx * 4);
            float q4[4] = {qv.x, qv.y, qv.z, qv.w};
            float k4[4] = {kv.x, kv.y, kv.z, kv.w};
            #pragma unroll
            for (int i = 0; i < 4; i++)
                #pragma unroll
                for (int j = 0; j < 4; j++) s[i][j] = fmaf(q4[i], k4[j], s[i][j]);
        }
        #pragma unroll
        for (int i = 0; i < 4; i++) {
            float4 e;
            e.x = __expf(s[i][0]); e.y = __expf(s[i][1]);
            e.z = __expf(s[i][2]); e.w = __expf(s[i][3]);
            *(float4*)(es + (ty * 4 + i) * 68 + tx * 4) = e;
        }
        __syncthreads();

        // stage2: acc[n][o] += es[n][m] * ws[m][o]
        #pragma unroll 4
        for (int m = 0; m < 64; m++) {
            float4 wv = *(const float4*)(ws + m * 40 + oid * 4);
            float e0 = es[(nid * 2 + 0) * 68 + m];
            float e1 = es[(nid * 2 + 1) * 68 + m];
            acc[0][0] = fmaf(e0, wv.x, acc[0][0]);
            acc[0][1] = fmaf(e0, wv.y, acc[0][1]);
            acc[0][2] = fmaf(e0, wv.z, acc[0][2]);
            acc[0][3] = fmaf(e0, wv.w, acc[0][3]);
            acc[1][0] = fmaf(e1, wv.x, acc[1][0]);
            acc[1][1] = fmaf(e1, wv.y, acc[1][1]);
            acc[1][2] = fmaf(e1, wv.z, acc[1][2]);
            acc[1][3] = fmaf(e1, wv.w, acc[1][3]);
        }
    }

    // epilogue: final[o][n] = y[n][o] + acc  (gamma & 1/Z folded into ws)
    const float* yin = g_y + ((size_t)b * HW + n0) * DHALF;
    #pragma unroll
    for (int r = 0; r < 2; r++) {
        int n = nid * 2 + r;
        #pragma unroll
        for (int j = 0; j < 4; j++) {
            int o = oid * 4 + j;
            out[(size_t)(b * 32 + o) * HW + n0 + n] = yin[n * 32 + o] + acc[r][j];
        }
    }
}

// ---------------------------------------------------------------------------
// launch
// ---------------------------------------------------------------------------
extern "C" void kernel_launch(void* const* d_in, const int* in_sizes, int n_in,
                              void* d_out, int out_size) {
    const float* x1    = (const float*)d_in[0];
    const float* x2    = (const float*)d_in[1];
    const float* Wq    = (const float*)d_in[2];
    const float* bq    = (const float*)d_in[3];
    const float* Wk    = (const float*)d_in[4];
    const float* bk    = (const float*)d_in[5];
    const float* Wv    = (const float*)d_in[6];
    const float* Wsc   = (const float*)d_in[7];
    const float* gamma = (const float*)d_in[8];
    float* out = (float*)d_out;

    k0_wu<<<8, 256>>>(Wsc, Wv);
    dim3 g1(HW / 128, BATCH);
    k1_proj<<<g1, 256>>>(x1, x2, Wq, bq, Wk, bk, Wsc);
    dim3 g2(HW / 64, BATCH);
    k2_stats<<<g2, 256>>>(gamma);
    dim3 g3(HW / 64, BATCH);
    k3_out<<<g3, 256>>>(out);
}

// round 3
// speedup vs baseline: 3.8701x; 3.8701x over previous
#include <cuda_runtime.h>
#include <cstdint>
#include <math.h>

// Shapes: B=8, C=64, H=W=64, HW=4096, D=C/2=32
#define BATCH 8
#define HW    4096
#define DH    32

// Scratch (device globals)
__device__ float g_qT[BATCH * DH * HW];   // [b][d][n]  tf32-rounded
__device__ float g_kT[BATCH * DH * HW];   // [b][d][m]  tf32-rounded
__device__ float g_u [BATCH * HW * DH];   // [b][m][o]  u = (Wsc@Wv)@x
__device__ float g_y [BATCH * HW * DH];   // [b][n][o]  y = Wsc@x
__device__ float g_zinv[BATCH * HW];      // gamma / Z[m]
__device__ float g_wu[DH * 64];           // Wsc@Wv

// ---------------------------------------------------------------------------
// helpers
// ---------------------------------------------------------------------------
__device__ __forceinline__ uint32_t f2tf(float f) {
    uint32_t u; asm("cvt.rna.tf32.f32 %0, %1;" : "=r"(u) : "f"(f)); return u;
}
__device__ __forceinline__ uint32_t packh2(float hi, float lo) {
    uint32_t d; asm("cvt.rn.f16x2.f32 %0, %1, %2;" : "=r"(d) : "f"(hi), "f"(lo)); return d;
}
// D += A*B, A=m16k8 tf32 (rows=M), B=k8n8 tf32 (rows=K)
__device__ __forceinline__ void mma_tf32(float* d, const uint32_t* a, uint32_t b0, uint32_t b1) {
    asm volatile("mma.sync.aligned.m16n8k8.row.col.f32.tf32.tf32.f32 "
        "{%0,%1,%2,%3}, {%4,%5,%6,%7}, {%8,%9}, {%0,%1,%2,%3};"
        : "+f"(d[0]), "+f"(d[1]), "+f"(d[2]), "+f"(d[3])
        : "r"(a[0]), "r"(a[1]), "r"(a[2]), "r"(a[3]), "r"(b0), "r"(b1));
}
// D += A*B, f16 m16n8k16
__device__ __forceinline__ void mma_f16(float* d, const uint32_t* a, uint32_t b0, uint32_t b1) {
    asm volatile("mma.sync.aligned.m16n8k16.row.col.f32.f16.f16.f32 "
        "{%0,%1,%2,%3}, {%4,%5,%6,%7}, {%8,%9}, {%0,%1,%2,%3};"
        : "+f"(d[0]), "+f"(d[1]), "+f"(d[2]), "+f"(d[3])
        : "r"(a[0]), "r"(a[1]), "r"(a[2]), "r"(a[3]), "r"(b0), "r"(b1));
}

// ---------------------------------------------------------------------------
// K0: Wu = Wsc @ Wv  (32x64)
// ---------------------------------------------------------------------------
__global__ __launch_bounds__(256) void k0_wu(const float* __restrict__ Wsc,
                                             const float* __restrict__ Wv) {
    int idx = blockIdx.x * 256 + threadIdx.x;
    if (idx < DH * 64) {
        int p = idx >> 6, c = idx & 63;
        float s = 0.f;
        #pragma unroll 8
        for (int t = 0; t < 64; t++) s = fmaf(Wsc[p * 64 + t], Wv[t * 64 + c], s);
        g_wu[idx] = s;
    }
}

// ---------------------------------------------------------------------------
// K1: projections. grid (64 px-blocks, 8 b), 256 thr. px-block = 64 pixels.
// q,k -> transposed tf32-rounded [d][n]; u,y -> row-major [n][o].
// ---------------------------------------------------------------------------
__global__ __launch_bounds__(256) void k1_proj(
    const float* __restrict__ x1, const float* __restrict__ x2,
    const float* __restrict__ Wq, const float* __restrict__ bq,
    const float* __restrict__ Wk, const float* __restrict__ bk,
    const float* __restrict__ Wsc) {
    __shared__ float xs[64 * 64];      // [c][px] 16KB
    __shared__ float wsm[64 * 32];     // [c][o]  8KB
    __shared__ float stg[64 * 36];     // stage   9.2KB (pad 33 for q/k, 36 for u/y)

    int b = blockIdx.y, n0 = blockIdx.x * 64, t = threadIdx.x;

    #pragma unroll
    for (int i = 0; i < 4; i++) {
        int idx = t + i * 256;            // 1024 f4: c = idx>>4, pg = idx&15
        int c = idx >> 4, pg = idx & 15;
        const float* src = (c < 32) ? (x1 + (size_t)(b * 32 + c) * HW)
                                    : (x2 + (size_t)(b * 32 + (c - 32)) * HW);
        *(float4*)(xs + c * 64 + pg * 4) = *(const float4*)(src + n0 + pg * 4);
    }

    int d = t & 31;
    int pxb = (t >> 5) * 8;
    int wrp = t >> 5, ln = t & 31;

    for (int p = 0; p < 4; p++) {
        const float* W = (p == 0) ? Wq : (p == 1) ? Wk : (p == 2) ? g_wu : Wsc;
        __syncthreads();                  // wsm/stg reuse vs previous iter
        #pragma unroll
        for (int i = 0; i < 8; i++) {
            int idx = t + i * 256;
            int o = idx >> 6, c = idx & 63;
            wsm[c * 32 + o] = W[idx];
        }
        __syncthreads();

        float bias = (p == 0) ? bq[d] : (p == 1) ? bk[d] : 0.f;
        float acc[8];
        #pragma unroll
        for (int j = 0; j < 8; j++) acc[j] = bias;
        for (int c = 0; c < 64; c++) {
            float wv = wsm[c * 32 + d];
            const float* xr = xs + c * 64 + pxb;
            #pragma unroll
            for (int j = 0; j < 8; j++) acc[j] = fmaf(wv, xr[j], acc[j]);
        }

        if (p < 2) {
            #pragma unroll
            for (int j = 0; j < 8; j++)
                stg[(pxb + j) * 33 + d] = __uint_as_float(f2tf(acc[j]));
        } else {
            #pragma unroll
            for (int j = 0; j < 8; j++) stg[(pxb + j) * 36 + d] = acc[j];
        }
        __syncthreads();

        if (p < 2) {
            float* dstT = ((p == 0) ? g_qT : g_kT) + (size_t)b * DH * HW;
            #pragma unroll
            for (int ci = 0; ci < 4; ci++) {
                int dd = wrp * 4 + ci;
                float v0 = stg[ln * 33 + dd];
                float v1 = stg[(ln + 32) * 33 + dd];
                dstT[(size_t)dd * HW + n0 + ln] = v0;
                dstT[(size_t)dd * HW + n0 + ln + 32] = v1;
            }
        } else {
            float* dst = ((p == 2) ? g_u : g_y) + ((size_t)b * HW + n0) * DH;
            #pragma unroll
            for (int i = 0; i < 2; i++) {
                int idx = t + i * 256;        // 512 f4
                int px = idx >> 3, og = idx & 7;
                *(float4*)(dst + px * 32 + og * 4) = *(float4*)(stg + px * 36 + og * 4);
            }
        }
    }
}

// ---------------------------------------------------------------------------
// kA: Z[m] = sum_n exp(q_n . k_m); store gamma/Z.
// grid (32 m-blocks, 8 b), 256 thr (8 warps x 16 m-rows resident A-frags).
// ---------------------------------------------------------------------------
__device__ __forceinline__ void fillA(float* dst, const float* qt, int nbase, int t) {
    #pragma unroll
    for (int i = 0; i < 4; i++) {
        int idx = t + i * 256;            // 1024: d = idx>>5, nc = (idx&31)*4
        int dd = idx >> 5, nc = (idx & 31) << 2;
        *(float4*)(dst + dd * 136 + nc) = *(const float4*)(qt + (size_t)dd * HW + nbase + nc);
    }
}

__global__ __launch_bounds__(256) void kA_stats(const float* __restrict__ gamma) {
    extern __shared__ float sm[];         // qT 2 bufs [32][136] = 34816B
    const int t = threadIdx.x, wrp = t >> 5, ln = t & 31, g = ln >> 2, c = ln & 3;
    const int b = blockIdx.y, m0 = blockIdx.x * 128;
    const int mrow = m0 + wrp * 16;

    const float* kt = g_kT + (size_t)b * DH * HW;
    uint32_t a[4][4];
    #pragma unroll
    for (int ks = 0; ks < 4; ks++) {
        a[ks][0] = __float_as_uint(kt[(size_t)(ks * 8 + c) * HW + mrow + g]);
        a[ks][1] = __float_as_uint(kt[(size_t)(ks * 8 + c) * HW + mrow + g + 8]);
        a[ks][2] = __float_as_uint(kt[(size_t)(ks * 8 + c + 4) * HW + mrow + g]);
        a[ks][3] = __float_as_uint(kt[(size_t)(ks * 8 + c + 4) * HW + mrow + g + 8]);
    }

    const float* qt = g_qT + (size_t)b * DH * HW;
    float z0 = 0.f, z1 = 0.f;

    fillA(sm, qt, 0, t);
    __syncthreads();
    for (int ch = 0; ch < 32; ch++) {
        if (ch + 1 < 32) fillA(sm + ((ch + 1) & 1) * 32 * 136, qt, (ch + 1) * 128, t);
        __syncthreads();
        const float* qb = sm + (ch & 1) * 32 * 136;
        #pragma unroll 4
        for (int ns = 0; ns < 16; ns++) {
            float s[4] = {0.f, 0.f, 0.f, 0.f};
            #pragma unroll
            for (int ks = 0; ks < 4; ks++) {
                uint32_t b0 = __float_as_uint(qb[(ks * 8 + c) * 136 + ns * 8 + g]);
                uint32_t b1 = __float_as_uint(qb[(ks * 8 + c + 4) * 136 + ns * 8 + g]);
                mma_tf32(s, a[ks], b0, b1);
            }
            z0 += __expf(s[0]) + __expf(s[1]);
            z1 += __expf(s[2]) + __expf(s[3]);
        }
        __syncthreads();
    }

    z0 += __shfl_down_sync(0xffffffffu, z0, 2);
    z0 += __shfl_down_sync(0xffffffffu, z0, 1);
    z1 += __shfl_down_sync(0xffffffffu, z1, 2);
    z1 += __shfl_down_sync(0xffffffffu, z1, 1);
    if (c == 0) {
        float ga = gamma[0];
        g_zinv[b * HW + mrow + g]     = ga / z0;
        g_zinv[b * HW + mrow + g + 8] = ga / z1;
    }
}

// ---------------------------------------------------------------------------
// kB: out[b,o,n] = y[n,o] + sum_m exp(q_n.k_m) * u[m,o] * (gamma/Z[m])
// grid (32 n-blocks, 8 b), 256 thr. q A-frags resident; m chunks of 64.
// PV in f16 (w scaled by 2^14; undone in epilogue).
// ---------------------------------------------------------------------------
__device__ __forceinline__ void fillB(float* kbuf, uint32_t* wbuf, int b, int ch, int t) {
    const int m0 = ch * 64;
    const float* kt = g_kT + (size_t)b * DH * HW;
    #pragma unroll
    for (int i = 0; i < 2; i++) {
        int idx = t + i * 256;            // 512 f4: d = idx>>4, mc = (idx&15)*4
        int dd = idx >> 4, mc = (idx & 15) << 2;
        *(float4*)(kbuf + dd * 72 + mc) = *(const float4*)(kt + (size_t)dd * HW + m0 + mc);
    }
    const float* ub = g_u + ((size_t)b * HW + m0) * DH;
    const float* zb = g_zinv + b * HW + m0;
    #pragma unroll
    for (int i = 0; i < 4; i++) {
        int idx = t + i * 256;            // pair = idx>>5, o = idx&31
        int p = idx >> 5, o = idx & 31;
        float zi0 = zb[2 * p] * 16384.f, zi1 = zb[2 * p + 1] * 16384.f;
        float u0 = ub[(2 * p) * 32 + o] * zi0;
        float u1 = ub[(2 * p + 1) * 32 + o] * zi1;
        wbuf[p * 40 + o] = packh2(u1, u0);   // lo = even m, hi = odd m
    }
}

__global__ __launch_bounds__(256) void kB_out(float* __restrict__ out) {
    extern __shared__ float sm[];
    float* kT = sm;                            // 2 x [32][72]  = 4608 floats
    uint32_t* w2 = (uint32_t*)(sm + 4608);     // 2 x [32][40]  = 2560 u32
    const int t = threadIdx.x, wrp = t >> 5, ln = t & 31, g = ln >> 2, c = ln & 3;
    const int b = blockIdx.y, n0 = blockIdx.x * 128;
    const int nrow = n0 + wrp * 16;

    const float* qt = g_qT + (size_t)b * DH * HW;
    uint32_t a[4][4];
    #pragma unroll
    for (int ks = 0; ks < 4; ks++) {
        a[ks][0] = __float_as_uint(qt[(size_t)(ks * 8 + c) * HW + nrow + g]);
        a[ks][1] = __float_as_uint(qt[(size_t)(ks * 8 + c) * HW + nrow + g + 8]);
        a[ks][2] = __float_as_uint(qt[(size_t)(ks * 8 + c + 4) * HW + nrow + g]);
        a[ks][3] = __float_as_uint(qt[(size_t)(ks * 8 + c + 4) * HW + nrow + g + 8]);
    }

    float o0[4][4];
    #pragma unroll
    for (int j = 0; j < 4; j++)
        #pragma unroll
        for (int r = 0; r < 4; r++) o0[j][r] = 0.f;

    fillB(kT, w2, b, 0, t);
    __syncthreads();
    for (int ch = 0; ch < 64; ch++) {
        if (ch + 1 < 64)
            fillB(kT + ((ch + 1) & 1) * 2304, w2 + ((ch + 1) & 1) * 1280, b, ch + 1, t);
        __syncthreads();
        const float* kc = kT + (ch & 1) * 2304;
        const uint32_t* wc = w2 + (ch & 1) * 1280;

        uint32_t pk[4];
        #pragma unroll
        for (int sub = 0; sub < 8; sub++) {
            float s[4] = {0.f, 0.f, 0.f, 0.f};
            #pragma unroll
            for (int ks = 0; ks < 4; ks++) {
                uint32_t b0 = __float_as_uint(kc[(ks * 8 + c) * 72 + sub * 8 + g]);
                uint32_t b1 = __float_as_uint(kc[(ks * 8 + c + 4) * 72 + sub * 8 + g]);
                mma_tf32(s, a[ks], b0, b1);
            }
            float e0 = __expf(s[0]), e1 = __expf(s[1]);
            float e2 = __expf(s[2]), e3 = __expf(s[3]);
            int h = sub & 1;
            pk[2 * h]     = packh2(e1, e0);   // row g,   cols 2c,2c+1
            pk[2 * h + 1] = packh2(e3, e2);   // row g+8
            if (h) {
                int pb = (sub >> 1) * 8;
                #pragma unroll
                for (int j = 0; j < 4; j++) {
                    uint32_t wb0 = wc[(pb + c) * 40 + j * 8 + g];
                    uint32_t wb1 = wc[(pb + c + 4) * 40 + j * 8 + g];
                    mma_f16(o0[j], pk, wb0, wb1);
                }
            }
        }
        __syncthreads();
    }

    // epilogue: stage [128 n][33] (aliases kT/w2, all reads done), add y, unscale
    float* stg = sm;
    const float* yb = g_y + ((size_t)b * HW + n0) * DH;
    const float S = 1.0f / 16384.0f;
    const int r0 = wrp * 16 + g, r1 = r0 + 8;
    #pragma unroll
    for (int j = 0; j < 4; j++) {
        int o = j * 8 + 2 * c;
        stg[r0 * 33 + o]     = yb[r0 * 32 + o]     + o0[j][0] * S;
        stg[r0 * 33 + o + 1] = yb[r0 * 32 + o + 1] + o0[j][1] * S;
        stg[r1 * 33 + o]     = yb[r1 * 32 + o]     + o0[j][2] * S;
        stg[r1 * 33 + o + 1] = yb[r1 * 32 + o + 1] + o0[j][3] * S;
    }
    __syncthreads();
    #pragma unroll
    for (int ci = 0; ci < 4; ci++) {
        int o = wrp * 4 + ci;
        float* dst = out + (size_t)(b * 32 + o) * HW + n0;
        #pragma unroll
        for (int pp = 0; pp < 4; pp++)
            dst[ln + 32 * pp] = stg[(ln + 32 * pp) * 33 + o];
    }
}

// ---------------------------------------------------------------------------
// launch
// ---------------------------------------------------------------------------
extern "C" void kernel_launch(void* const* d_in, const int* in_sizes, int n_in,
                              void* d_out, int out_size) {
    const float* x1    = (const float*)d_in[0];
    const float* x2    = (const float*)d_in[1];
    const float* Wq    = (const float*)d_in[2];
    const float* bq    = (const float*)d_in[3];
    const float* Wk    = (const float*)d_in[4];
    const float* bk    = (const float*)d_in[5];
    const float* Wv    = (const float*)d_in[6];
    const float* Wsc   = (const float*)d_in[7];
    const float* gamma = (const float*)d_in[8];
    float* out = (float*)d_out;

    k0_wu<<<8, 256>>>(Wsc, Wv);
    dim3 g1(HW / 64, BATCH);
    k1_proj<<<g1, 256>>>(x1, x2, Wq, bq, Wk, bk, Wsc);
    dim3 g2(HW / 128, BATCH);
    kA_stats<<<g2, 256, 2 * 32 * 136 * 4>>>(gamma);
    dim3 g3(HW / 128, BATCH);
    kB_out<<<g3, 256, (4608 + 2560) * 4>>>(out);
}

// round 4
// speedup vs baseline: 5.1414x; 1.3285x over previous
#include <cuda_runtime.h>
#include <cstdint>
#include <math.h>

// Shapes: B=8, C=64, H=W=64, HW=4096, D=C/2=32
#define BATCH 8
#define HW    4096
#define DH    32
#define LOG2E 1.4426950408889634f

// Scratch (device globals)
__device__ uint32_t g_qh[BATCH * 16 * HW];  // [b][dpair][n] f16x2 (log2e-scaled)
__device__ uint32_t g_kh[BATCH * 16 * HW];  // [b][dpair][m] f16x2
__device__ float g_u [BATCH * HW * DH];     // [b][m][o]  u = (Wsc@Wv)@x
__device__ float g_y [BATCH * HW * DH];     // [b][n][o]  y = Wsc@x
__device__ float g_zinv[BATCH * HW];        // gamma / Z[m]
__device__ float g_wu[DH * 64];             // Wsc@Wv

// ---------------------------------------------------------------------------
// helpers
// ---------------------------------------------------------------------------
__device__ __forceinline__ uint32_t packh2(float hi, float lo) {
    uint32_t d; asm("cvt.rn.f16x2.f32 %0, %1, %2;" : "=r"(d) : "f"(hi), "f"(lo)); return d;
}
__device__ __forceinline__ uint32_t ex2h2(uint32_t x) {
    uint32_t d; asm("ex2.approx.f16x2 %0, %1;" : "=r"(d) : "r"(x)); return d;
}
// D += A*B, f16 m16n8k16
__device__ __forceinline__ void mma_f16(float* d, const uint32_t* a, uint32_t b0, uint32_t b1) {
    asm volatile("mma.sync.aligned.m16n8k16.row.col.f32.f16.f16.f32 "
        "{%0,%1,%2,%3}, {%4,%5,%6,%7}, {%8,%9}, {%0,%1,%2,%3};"
        : "+f"(d[0]), "+f"(d[1]), "+f"(d[2]), "+f"(d[3])
        : "r"(a[0]), "r"(a[1]), "r"(a[2]), "r"(a[3]), "r"(b0), "r"(b1));
}

// ---------------------------------------------------------------------------
// K0: Wu = Wsc @ Wv  (32x64)
// ---------------------------------------------------------------------------
__global__ __launch_bounds__(256) void k0_wu(const float* __restrict__ Wsc,
                                             const float* __restrict__ Wv) {
    int idx = blockIdx.x * 256 + threadIdx.x;
    if (idx < DH * 64) {
        int p = idx >> 6, c = idx & 63;
        float s = 0.f;
        #pragma unroll 8
        for (int t = 0; t < 64; t++) s = fmaf(Wsc[p * 64 + t], Wv[t * 64 + c], s);
        g_wu[idx] = s;
    }
}

// ---------------------------------------------------------------------------
// K1: projections. grid (64 px-blocks, 8 b), 256 thr.
// q (log2e-scaled), k -> packed f16x2 [dpair][n]; u,y -> row-major f32 [n][o].
// ---------------------------------------------------------------------------
__global__ __launch_bounds__(256) void k1_proj(
    const float* __restrict__ x1, const float* __restrict__ x2,
    const float* __restrict__ Wq, const float* __restrict__ bq,
    const float* __restrict__ Wk, const float* __restrict__ bk,
    const float* __restrict__ Wsc) {
    __shared__ float xs[64 * 64];
    __shared__ float wsm[64 * 32];
    __shared__ float stg[64 * 36];

    int b = blockIdx.y, n0 = blockIdx.x * 64, t = threadIdx.x;

    #pragma unroll
    for (int i = 0; i < 4; i++) {
        int idx = t + i * 256;
        int c = idx >> 4, pg = idx & 15;
        const float* src = (c < 32) ? (x1 + (size_t)(b * 32 + c) * HW)
                                    : (x2 + (size_t)(b * 32 + (c - 32)) * HW);
        *(float4*)(xs + c * 64 + pg * 4) = *(const float4*)(src + n0 + pg * 4);
    }

    int d = t & 31;
    int pxb = (t >> 5) * 8;

    for (int p = 0; p < 4; p++) {
        const float* W = (p == 0) ? Wq : (p == 1) ? Wk : (p == 2) ? g_wu : Wsc;
        __syncthreads();
        #pragma unroll
        for (int i = 0; i < 8; i++) {
            int idx = t + i * 256;
            int o = idx >> 6, c = idx & 63;
            wsm[c * 32 + o] = W[idx];
        }
        __syncthreads();

        float bias = (p == 0) ? bq[d] : (p == 1) ? bk[d] : 0.f;
        float acc[8];
        #pragma unroll
        for (int j = 0; j < 8; j++) acc[j] = bias;
        for (int c = 0; c < 64; c++) {
            float wv = wsm[c * 32 + d];
            const float* xr = xs + c * 64 + pxb;
            #pragma unroll
            for (int j = 0; j < 8; j++) acc[j] = fmaf(wv, xr[j], acc[j]);
        }

        if (p == 0) {
            #pragma unroll
            for (int j = 0; j < 8; j++) stg[(pxb + j) * 33 + d] = acc[j] * LOG2E;
        } else if (p == 1) {
            #pragma unroll
            for (int j = 0; j < 8; j++) stg[(pxb + j) * 33 + d] = acc[j];
        } else {
            #pragma unroll
            for (int j = 0; j < 8; j++) stg[(pxb + j) * 36 + d] = acc[j];
        }
        __syncthreads();

        if (p < 2) {
            uint32_t* dstT = ((p == 0) ? g_qh : g_kh) + (size_t)b * 16 * HW;
            #pragma unroll
            for (int i = 0; i < 4; i++) {
                int idx = t + i * 256;            // 1024: pr = idx>>6, px = idx&63
                int pr = idx >> 6, px = idx & 63;
                uint32_t v = packh2(stg[px * 33 + 2 * pr + 1], stg[px * 33 + 2 * pr]);
                dstT[(size_t)pr * HW + n0 + px] = v;
            }
        } else {
            float* dst = ((p == 2) ? g_u : g_y) + ((size_t)b * HW + n0) * DH;
            #pragma unroll
            for (int i = 0; i < 2; i++) {
                int idx = t + i * 256;
                int px = idx >> 3, og = idx & 7;
                *(float4*)(dst + px * 32 + og * 4) = *(float4*)(stg + px * 36 + og * 4);
            }
        }
    }
}

// ---------------------------------------------------------------------------
// kA: Z[m] = sum_n 2^(q'_n . k_m). grid (32 m-blocks, 8 b), 256 thr.
// A = resident k rows (m16/warp). Column sums via ones-MMA into f32 acc.
// ---------------------------------------------------------------------------
__device__ __forceinline__ void fillQ(uint32_t* dst, const uint32_t* qp, int nbase, int t) {
    #pragma unroll
    for (int i = 0; i < 2; i++) {
        int idx = t + i * 256;            // 512 u4: row = idx>>5, nc = (idx&31)*4
        int row = idx >> 5, nc = (idx & 31) << 2;
        *(uint4*)(dst + row * 136 + nc) = *(const uint4*)(qp + (size_t)row * HW + nbase + nc);
    }
}

__global__ __launch_bounds__(256) void kA_stats(const float* __restrict__ gamma) {
    extern __shared__ uint32_t smA[];     // 2 x [16][136] u32
    const int t = threadIdx.x, wrp = t >> 5, ln = t & 31, g = ln >> 2, c = ln & 3;
    const int b = blockIdx.y, m0 = blockIdx.x * 128;
    const int mrow = m0 + wrp * 16;
    const uint32_t ONES = 0x3C003C00u;

    const uint32_t* kp = g_kh + (size_t)b * 16 * HW;
    uint32_t a[2][4];
    #pragma unroll
    for (int ks = 0; ks < 2; ks++) {
        a[ks][0] = kp[(size_t)(ks * 8 + c) * HW + mrow + g];
        a[ks][1] = kp[(size_t)(ks * 8 + c) * HW + mrow + g + 8];
        a[ks][2] = kp[(size_t)(ks * 8 + c + 4) * HW + mrow + g];
        a[ks][3] = kp[(size_t)(ks * 8 + c + 4) * HW + mrow + g + 8];
    }

    const uint32_t* qp = g_qh + (size_t)b * 16 * HW;
    float zacc[4] = {0.f, 0.f, 0.f, 0.f};

    fillQ(smA, qp, 0, t);
    __syncthreads();
    for (int ch = 0; ch < 32; ch++) {
        if (ch + 1 < 32) fillQ(smA + ((ch + 1) & 1) * 16 * 136, qp, (ch + 1) * 128, t);
        __syncthreads();
        const uint32_t* qb = smA + (ch & 1) * 16 * 136;
        uint32_t pk[4];
        #pragma unroll 4
        for (int ns = 0; ns < 16; ns++) {
            float s[4] = {0.f, 0.f, 0.f, 0.f};
            #pragma unroll
            for (int ks = 0; ks < 2; ks++) {
                uint32_t b0 = qb[(ks * 8 + c) * 136 + ns * 8 + g];
                uint32_t b1 = qb[(ks * 8 + c + 4) * 136 + ns * 8 + g];
                mma_f16(s, a[ks], b0, b1);
            }
            int h = ns & 1;
            pk[2 * h]     = ex2h2(packh2(s[1], s[0]));
            pk[2 * h + 1] = ex2h2(packh2(s[3], s[2]));
            if (h) mma_f16(zacc, pk, ONES, ONES);
        }
        __syncthreads();
    }

    if (c == 0) {
        float ga = gamma[0];
        g_zinv[b * HW + mrow + g]     = ga / zacc[0];
        g_zinv[b * HW + mrow + g + 8] = ga / zacc[2];
    }
}

// ---------------------------------------------------------------------------
// kB: out[b,o,n] = y[n,o] + sum_m 2^(q'_n.k_m) * u[m,o] * (gamma/Z[m])
// grid (32 n-blocks, 8 b), 256 thr. q A-frags resident; m chunks of 64.
// PV in f16 (w scaled by 2^14; undone in epilogue).
// ---------------------------------------------------------------------------
__device__ __forceinline__ void fillB(uint32_t* kbuf, uint32_t* wbuf, int b, int ch, int t) {
    const int m0 = ch * 64;
    const uint32_t* kp = g_kh + (size_t)b * 16 * HW;
    {
        int row = t >> 4, mc = (t & 15) << 2;   // 256 u4: [16][64]
        *(uint4*)(kbuf + row * 72 + mc) = *(const uint4*)(kp + (size_t)row * HW + m0 + mc);
    }
    const float* ub = g_u + ((size_t)b * HW + m0) * DH;
    const float* zb = g_zinv + b * HW + m0;
    #pragma unroll
    for (int i = 0; i < 4; i++) {
        int idx = t + i * 256;            // p = idx>>5, o = idx&31
        int p = idx >> 5, o = idx & 31;
        float zi0 = zb[2 * p] * 16384.f, zi1 = zb[2 * p + 1] * 16384.f;
        float u0 = ub[(2 * p) * 32 + o] * zi0;
        float u1 = ub[(2 * p + 1) * 32 + o] * zi1;
        wbuf[p * 40 + o] = packh2(u1, u0);   // lo = even m, hi = odd m
    }
}

__global__ __launch_bounds__(256) void kB_out(float* __restrict__ out) {
    extern __shared__ uint32_t smB[];
    uint32_t* kT = smB;                        // 2 x [16][72] = 2304 u32
    uint32_t* w2 = smB + 2304;                 // 2 x [32][40] = 2560 u32
    const int t = threadIdx.x, wrp = t >> 5, ln = t & 31, g = ln >> 2, c = ln & 3;
    const int b = blockIdx.y, n0 = blockIdx.x * 128;
    const int nrow = n0 + wrp * 16;

    const uint32_t* qp = g_qh + (size_t)b * 16 * HW;
    uint32_t a[2][4];
    #pragma unroll
    for (int ks = 0; ks < 2; ks++) {
        a[ks][0] = qp[(size_t)(ks * 8 + c) * HW + nrow + g];
        a[ks][1] = qp[(size_t)(ks * 8 + c) * HW + nrow + g + 8];
        a[ks][2] = qp[(size_t)(ks * 8 + c + 4) * HW + nrow + g];
        a[ks][3] = qp[(size_t)(ks * 8 + c + 4) * HW + nrow + g + 8];
    }

    float o0[4][4];
    #pragma unroll
    for (int j = 0; j < 4; j++)
        #pragma unroll
        for (int r = 0; r < 4; r++) o0[j][r] = 0.f;

    fillB(kT, w2, b, 0, t);
    __syncthreads();
    for (int ch = 0; ch < 64; ch++) {
        if (ch + 1 < 64)
            fillB(kT + ((ch + 1) & 1) * 1152, w2 + ((ch + 1) & 1) * 1280, b, ch + 1, t);
        __syncthreads();
        const uint32_t* kc = kT + (ch & 1) * 1152;
        const uint32_t* wc = w2 + (ch & 1) * 1280;

        uint32_t pk[4];
        #pragma unroll
        for (int sub = 0; sub < 8; sub++) {
            float s[4] = {0.f, 0.f, 0.f, 0.f};
            #pragma unroll
            for (int ks = 0; ks < 2; ks++) {
                uint32_t b0 = kc[(ks * 8 + c) * 72 + sub * 8 + g];
                uint32_t b1 = kc[(ks * 8 + c + 4) * 72 + sub * 8 + g];
                mma_f16(s, a[ks], b0, b1);
            }
            int h = sub & 1;
            pk[2 * h]     = ex2h2(packh2(s[1], s[0]));
            pk[2 * h + 1] = ex2h2(packh2(s[3], s[2]));
            if (h) {
                int pb = (sub >> 1) * 8;
                #pragma unroll
                for (int j = 0; j < 4; j++) {
                    uint32_t wb0 = wc[(pb + c) * 40 + j * 8 + g];
                    uint32_t wb1 = wc[(pb + c + 4) * 40 + j * 8 + g];
                    mma_f16(o0[j], pk, wb0, wb1);
                }
            }
        }
        __syncthreads();
    }

    // epilogue: stage [128 n][33] f32 (aliases kT/w2), add y, unscale
    float* stg = (float*)smB;
    const float* yb = g_y + ((size_t)b * HW + n0) * DH;
    const float S = 1.0f / 16384.0f;
    const int r0 = wrp * 16 + g, r1 = r0 + 8;
    #pragma unroll
    for (int j = 0; j < 4; j++) {
        int o = j * 8 + 2 * c;
        stg[r0 * 33 + o]     = yb[r0 * 32 + o]     + o0[j][0] * S;
        stg[r0 * 33 + o + 1] = yb[r0 * 32 + o + 1] + o0[j][1] * S;
        stg[r1 * 33 + o]     = yb[r1 * 32 + o]     + o0[j][2] * S;
        stg[r1 * 33 + o + 1] = yb[r1 * 32 + o + 1] + o0[j][3] * S;
    }
    __syncthreads();
    #pragma unroll
    for (int ci = 0; ci < 4; ci++) {
        int o = wrp * 4 + ci;
        float* dst = out + (size_t)(b * 32 + o) * HW + n0;
        #pragma unroll
        for (int pp = 0; pp < 4; pp++)
            dst[ln + 32 * pp] = stg[(ln + 32 * pp) * 33 + o];
    }
}

// ---------------------------------------------------------------------------
// launch
// ---------------------------------------------------------------------------
extern "C" void kernel_launch(void* const* d_in, const int* in_sizes, int n_in,
                              void* d_out, int out_size) {
    const float* x1    = (const float*)d_in[0];
    const float* x2    = (const float*)d_in[1];
    const float* Wq    = (const float*)d_in[2];
    const float* bq    = (const float*)d_in[3];
    const float* Wk    = (const float*)d_in[4];
    const float* bk    = (const float*)d_in[5];
    const float* Wv    = (const float*)d_in[6];
    const float* Wsc   = (const float*)d_in[7];
    const float* gamma = (const float*)d_in[8];
    float* out = (float*)d_out;

    k0_wu<<<8, 256>>>(Wsc, Wv);
    dim3 g1(HW / 64, BATCH);
    k1_proj<<<g1, 256>>>(x1, x2, Wq, bq, Wk, bk, Wsc);
    dim3 g2(HW / 128, BATCH);
    kA_stats<<<g2, 256, 2 * 16 * 136 * 4>>>(gamma);
    dim3 g3(HW / 128, BATCH);
    kB_out<<<g3, 256, (2304 + 2560) * 4>>>(out);
}

// round 5
// speedup vs baseline: 5.5858x; 1.0864x over previous
#include <cuda_runtime.h>
#include <cstdint>
#include <math.h>

// Shapes: B=8, C=64, H=W=64, HW=4096, D=C/2=32
#define BATCH 8
#define HW    4096
#define DH    32
#define LOG2E 1.4426950408889634f

// Scratch (device globals)
__device__ uint32_t g_qh[BATCH * 16 * HW];  // [b][dpair][n] f16x2 (log2e-scaled)
__device__ uint32_t g_kh[BATCH * 16 * HW];  // [b][dpair][m] f16x2
__device__ float    g_u [BATCH * HW * DH];  // [b][m][o]  u = (Wsc@Wv)@x
__device__ float    g_y [BATCH * HW * DH];  // [b][n][o]  y = Wsc@x
__device__ float    g_zinv[BATCH * HW];     // gamma / Z[m]
__device__ uint32_t g_w2[BATCH * (HW/2) * DH]; // [b][mpair][o] packed f16x2 of u*gamma/Z*2^14
__device__ float    g_wu[DH * 64];          // Wsc@Wv

// ---------------------------------------------------------------------------
// helpers
// ---------------------------------------------------------------------------
__device__ __forceinline__ uint32_t packh2(float hi, float lo) {
    uint32_t d; asm("cvt.rn.f16x2.f32 %0, %1, %2;" : "=r"(d) : "f"(hi), "f"(lo)); return d;
}
__device__ __forceinline__ uint32_t ex2h2(uint32_t x) {
    uint32_t d; asm("ex2.approx.f16x2 %0, %1;" : "=r"(d) : "r"(x)); return d;
}
__device__ __forceinline__ void mma_f16(float* d, const uint32_t* a, uint32_t b0, uint32_t b1) {
    asm volatile("mma.sync.aligned.m16n8k16.row.col.f32.f16.f16.f32 "
        "{%0,%1,%2,%3}, {%4,%5,%6,%7}, {%8,%9}, {%0,%1,%2,%3};"
        : "+f"(d[0]), "+f"(d[1]), "+f"(d[2]), "+f"(d[3])
        : "r"(a[0]), "r"(a[1]), "r"(a[2]), "r"(a[3]), "r"(b0), "r"(b1));
}

// ---------------------------------------------------------------------------
// K0: Wu = Wsc @ Wv  (32x64)
// ---------------------------------------------------------------------------
__global__ __launch_bounds__(256) void k0_wu(const float* __restrict__ Wsc,
                                             const float* __restrict__ Wv) {
    int idx = blockIdx.x * 256 + threadIdx.x;
    if (idx < DH * 64) {
        int p = idx >> 6, c = idx & 63;
        float s = 0.f;
        #pragma unroll 8
        for (int t = 0; t < 64; t++) s = fmaf(Wsc[p * 64 + t], Wv[t * 64 + c], s);
        g_wu[idx] = s;
    }
}

// ---------------------------------------------------------------------------
// K1: projections. grid (64 px-blocks, 8 b), 256 thr.
// ---------------------------------------------------------------------------
__global__ __launch_bounds__(256) void k1_proj(
    const float* __restrict__ x1, const float* __restrict__ x2,
    const float* __restrict__ Wq, const float* __restrict__ bq,
    const float* __restrict__ Wk, const float* __restrict__ bk,
    const float* __restrict__ Wsc) {
    __shared__ float xs[64 * 64];
    __shared__ float wsm[64 * 32];
    __shared__ float stg[64 * 36];

    int b = blockIdx.y, n0 = blockIdx.x * 64, t = threadIdx.x;

    #pragma unroll
    for (int i = 0; i < 4; i++) {
        int idx = t + i * 256;
        int c = idx >> 4, pg = idx & 15;
        const float* src = (c < 32) ? (x1 + (size_t)(b * 32 + c) * HW)
                                    : (x2 + (size_t)(b * 32 + (c - 32)) * HW);
        *(float4*)(xs + c * 64 + pg * 4) = *(const float4*)(src + n0 + pg * 4);
    }

    int d = t & 31;
    int pxb = (t >> 5) * 8;

    for (int p = 0; p < 4; p++) {
        const float* W = (p == 0) ? Wq : (p == 1) ? Wk : (p == 2) ? g_wu : Wsc;
        __syncthreads();
        #pragma unroll
        for (int i = 0; i < 8; i++) {
            int idx = t + i * 256;
            int o = idx >> 6, c = idx & 63;
            wsm[c * 32 + o] = W[idx];
        }
        __syncthreads();

        float bias = (p == 0) ? bq[d] : (p == 1) ? bk[d] : 0.f;
        float acc[8];
        #pragma unroll
        for (int j = 0; j < 8; j++) acc[j] = bias;
        for (int c = 0; c < 64; c++) {
            float wv = wsm[c * 32 + d];
            const float* xr = xs + c * 64 + pxb;
            #pragma unroll
            for (int j = 0; j < 8; j++) acc[j] = fmaf(wv, xr[j], acc[j]);
        }

        if (p == 0) {
            #pragma unroll
            for (int j = 0; j < 8; j++) stg[(pxb + j) * 33 + d] = acc[j] * LOG2E;
        } else if (p == 1) {
            #pragma unroll
            for (int j = 0; j < 8; j++) stg[(pxb + j) * 33 + d] = acc[j];
        } else {
            #pragma unroll
            for (int j = 0; j < 8; j++) stg[(pxb + j) * 36 + d] = acc[j];
        }
        __syncthreads();

        if (p < 2) {
            uint32_t* dstT = ((p == 0) ? g_qh : g_kh) + (size_t)b * 16 * HW;
            #pragma unroll
            for (int i = 0; i < 4; i++) {
                int idx = t + i * 256;
                int pr = idx >> 6, px = idx & 63;
                uint32_t v = packh2(stg[px * 33 + 2 * pr + 1], stg[px * 33 + 2 * pr]);
                dstT[(size_t)pr * HW + n0 + px] = v;
            }
        } else {
            float* dst = ((p == 2) ? g_u : g_y) + ((size_t)b * HW + n0) * DH;
            #pragma unroll
            for (int i = 0; i < 2; i++) {
                int idx = t + i * 256;
                int px = idx >> 3, og = idx & 7;
                *(float4*)(dst + px * 32 + og * 4) = *(float4*)(stg + px * 36 + og * 4);
            }
        }
    }
}

// ---------------------------------------------------------------------------
// kA: Z[m] = sum_n 2^(q'_n . k_m). grid (64 m-tiles, 8 b), 512 thr (16 warps).
// warp = (mblk 0..3, nq 0..3): 16 m-rows, quarter of n. 8 iters x 512-n window.
// ---------------------------------------------------------------------------
#define QST 520
__device__ __forceinline__ void fillQ(uint32_t* dst, const uint32_t* qp, int nbase, int t) {
    #pragma unroll
    for (int i = 0; i < 4; i++) {
        int idx = t + i * 512;            // 2048 u4: row = idx>>7, nc = (idx&127)*4
        int row = idx >> 7, nc = (idx & 127) << 2;
        *(uint4*)(dst + row * QST + nc) = *(const uint4*)(qp + (size_t)row * HW + nbase + nc);
    }
}

__global__ __launch_bounds__(512) void kA_stats(const float* __restrict__ gamma) {
    extern __shared__ uint32_t smA[];     // 2 x [16][520] u32 = 66560B
    const int t = threadIdx.x, w = t >> 5, ln = t & 31, g = ln >> 2, c = ln & 3;
    const int b = blockIdx.y, m0 = blockIdx.x * 64;
    const int mblk = w & 3, nq = w >> 2;
    const int mrow = m0 + mblk * 16;
    const uint32_t ONES = 0x3C003C00u;

    const uint32_t* kp = g_kh + (size_t)b * 16 * HW;
    uint32_t a[2][4];
    #pragma unroll
    for (int ks = 0; ks < 2; ks++) {
        a[ks][0] = kp[(size_t)(ks * 8 + c) * HW + mrow + g];
        a[ks][1] = kp[(size_t)(ks * 8 + c) * HW + mrow + g + 8];
        a[ks][2] = kp[(size_t)(ks * 8 + c + 4) * HW + mrow + g];
        a[ks][3] = kp[(size_t)(ks * 8 + c + 4) * HW + mrow + g + 8];
    }

    const uint32_t* qp = g_qh + (size_t)b * 16 * HW;
    float zacc[4] = {0.f, 0.f, 0.f, 0.f};

    fillQ(smA, qp, 0, t);
    __syncthreads();
    for (int it = 0; it < 8; it++) {
        if (it + 1 < 8) fillQ(smA + ((it + 1) & 1) * 16 * QST, qp, (it + 1) * 512, t);
        __syncthreads();
        const uint32_t* qb = smA + (it & 1) * 16 * QST + nq * 128;
        uint32_t pk[4];
        #pragma unroll
        for (int ns = 0; ns < 16; ns++) {
            float s[4] = {0.f, 0.f, 0.f, 0.f};
            #pragma unroll
            for (int ks = 0; ks < 2; ks++) {
                uint32_t b0 = qb[(ks * 8 + c) * QST + ns * 8 + g];
                uint32_t b1 = qb[(ks * 8 + c + 4) * QST + ns * 8 + g];
                mma_f16(s, a[ks], b0, b1);
            }
            int h = ns & 1;
            pk[2 * h]     = ex2h2(packh2(s[1], s[0]));
            pk[2 * h + 1] = ex2h2(packh2(s[3], s[2]));
            if (h) mma_f16(zacc, pk, ONES, ONES);
        }
        __syncthreads();
    }

    float* zp = (float*)smA;              // [4 quarters][68]
    if (c == 0) {
        zp[nq * 68 + mblk * 16 + g]     = zacc[0];
        zp[nq * 68 + mblk * 16 + g + 8] = zacc[2];
    }
    __syncthreads();
    if (t < 64) {
        float Z = zp[t] + zp[68 + t] + zp[136 + t] + zp[204 + t];
        g_zinv[b * HW + m0 + t] = gamma[0] / Z;
    }
}

// ---------------------------------------------------------------------------
// kW: precompute packed PV weights: g_w2[b][p][o] = f16x2(u*gamma/Z*2^14)
// ---------------------------------------------------------------------------
__global__ __launch_bounds__(256) void kW() {
    int idx = blockIdx.x * 256 + threadIdx.x;   // BATCH*2048*32 = 524288
    int o = idx & 31, p = (idx >> 5) & 2047, b = idx >> 16;
    const float* ub = g_u + ((size_t)b * HW + 2 * p) * DH;
    float z0 = g_zinv[b * HW + 2 * p] * 16384.f;
    float z1 = g_zinv[b * HW + 2 * p + 1] * 16384.f;
    g_w2[(size_t)b * (HW/2) * DH + p * 32 + o] = packh2(ub[32 + o] * z1, ub[o] * z0);
}

// ---------------------------------------------------------------------------
// kB: out[b,o,n] = y[n,o] + sum_m 2^(q'_n.k_m) * w[m,o].  grid (64 n-tiles, 8 b),
// 512 thr. warp = (nblk 0..3, mq 0..3): 16 n-rows, quarter of m.
// 16 iters x 256-m window; smem reduction over m-quarters at the end.
// ---------------------------------------------------------------------------
#define KST 264
#define WST 40
// smem u32 layout: k bufs @ 0 / 4224; w bufs @ 8448 / 13568; total 18688 u32 (74752B)
__device__ __forceinline__ void fillB(uint32_t* kbuf, uint32_t* wbuf,
                                      const uint32_t* kp, const uint32_t* wg,
                                      int m0, int t) {
    #pragma unroll
    for (int i = 0; i < 2; i++) {
        int idx = t + i * 512;            // 1024 u4: row = idx>>6, mc = (idx&63)*4
        int row = idx >> 6, mc = (idx & 63) << 2;
        *(uint4*)(kbuf + row * KST + mc) = *(const uint4*)(kp + (size_t)row * HW + m0 + mc);
    }
    #pragma unroll
    for (int i = 0; i < 2; i++) {
        int idx = t + i * 512;            // 1024 u4: p = idx>>3, og = (idx&7)*4
        int p = idx >> 3, og = (idx & 7) << 2;
        *(uint4*)(wbuf + p * WST + og) = *(const uint4*)(wg + ((size_t)(m0 >> 1) + p) * 32 + og);
    }
}

__global__ __launch_bounds__(512) void kB_out(float* __restrict__ out) {
    extern __shared__ uint32_t smB[];
    const int t = threadIdx.x, w = t >> 5, ln = t & 31, g = ln >> 2, c = ln & 3;
    const int b = blockIdx.y, n0 = blockIdx.x * 64;
    const int nblk = w & 3, mq = w >> 2;
    const int nrow = n0 + nblk * 16;

    const uint32_t* qp = g_qh + (size_t)b * 16 * HW;
    const uint32_t* kp = g_kh + (size_t)b * 16 * HW;
    const uint32_t* wg = g_w2 + (size_t)b * (HW/2) * DH;

    uint32_t a[2][4];
    #pragma unroll
    for (int ks = 0; ks < 2; ks++) {
        a[ks][0] = qp[(size_t)(ks * 8 + c) * HW + nrow + g];
        a[ks][1] = qp[(size_t)(ks * 8 + c) * HW + nrow + g + 8];
        a[ks][2] = qp[(size_t)(ks * 8 + c + 4) * HW + nrow + g];
        a[ks][3] = qp[(size_t)(ks * 8 + c + 4) * HW + nrow + g + 8];
    }

    float o0[4][4];
    #pragma unroll
    for (int j = 0; j < 4; j++)
        #pragma unroll
        for (int r = 0; r < 4; r++) o0[j][r] = 0.f;

    fillB(smB, smB + 8448, kp, wg, 0, t);
    __syncthreads();
    for (int it = 0; it < 16; it++) {
        if (it + 1 < 16)
            fillB(smB + ((it + 1) & 1) * 4224, smB + 8448 + ((it + 1) & 1) * 5120,
                  kp, wg, (it + 1) * 256, t);
        __syncthreads();
        const uint32_t* kc = smB + (it & 1) * 4224 + mq * 64;
        const uint32_t* wc = smB + 8448 + (it & 1) * 5120 + mq * 32 * WST;

        uint32_t pk[4];
        #pragma unroll
        for (int sub = 0; sub < 8; sub++) {
            float s[4] = {0.f, 0.f, 0.f, 0.f};
            #pragma unroll
            for (int ks = 0; ks < 2; ks++) {
                uint32_t b0 = kc[(ks * 8 + c) * KST + sub * 8 + g];
                uint32_t b1 = kc[(ks * 8 + c + 4) * KST + sub * 8 + g];
                mma_f16(s, a[ks], b0, b1);
            }
            int h = sub & 1;
            pk[2 * h]     = ex2h2(packh2(s[1], s[0]));
            pk[2 * h + 1] = ex2h2(packh2(s[3], s[2]));
            if (h) {
                int pb = (sub >> 1) * 8;
                #pragma unroll
                for (int j = 0; j < 4; j++) {
                    uint32_t wb0 = wc[(pb + c) * WST + j * 8 + g];
                    uint32_t wb1 = wc[(pb + c + 4) * WST + j * 8 + g];
                    mma_f16(o0[j], pk, wb0, wb1);
                }
            }
        }
        __syncthreads();
    }

    // cross-warp m-quarter reduction via smem
    float* part = (float*)smB;            // [16 warps][16 rows][33]
    float* myp = part + w * 528;
    #pragma unroll
    for (int j = 0; j < 4; j++) {
        int o = j * 8 + 2 * c;
        myp[g * 33 + o]           = o0[j][0];
        myp[g * 33 + o + 1]       = o0[j][1];
        myp[(g + 8) * 33 + o]     = o0[j][2];
        myp[(g + 8) * 33 + o + 1] = o0[j][3];
    }
    __syncthreads();

    float* stgf = part + 8448;            // [64 rows][33]
    if (mq == 0) {
        const float* yb = g_y + ((size_t)b * HW + nrow) * DH;
        const float S = 1.0f / 16384.0f;
        #pragma unroll
        for (int j = 0; j < 4; j++) {
            int o = j * 8 + 2 * c;
            #pragma unroll
            for (int rr = 0; rr < 2; rr++) {
                int r = g + rr * 8;
                float s0 = 0.f, s1 = 0.f;
                #pragma unroll
                for (int qq = 0; qq < 4; qq++) {
                    s0 += part[(nblk + 4 * qq) * 528 + r * 33 + o];
                    s1 += part[(nblk + 4 * qq) * 528 + r * 33 + o + 1];
                }
                stgf[(nblk * 16 + r) * 33 + o]     = yb[r * 32 + o]     + s0 * S;
                stgf[(nblk * 16 + r) * 33 + o + 1] = yb[r * 32 + o + 1] + s1 * S;
            }
        }
    }
    __syncthreads();

    {
        int o = t >> 4, ng = (t & 15) << 2;
        float4 v;
        v.x = stgf[(ng    ) * 33 + o];
        v.y = stgf[(ng + 1) * 33 + o];
        v.z = stgf[(ng + 2) * 33 + o];
        v.w = stgf[(ng + 3) * 33 + o];
        *(float4*)(out + (size_t)(b * 32 + o) * HW + n0 + ng) = v;
    }
}

// ---------------------------------------------------------------------------
// launch
// ---------------------------------------------------------------------------
extern "C" void kernel_launch(void* const* d_in, const int* in_sizes, int n_in,
                              void* d_out, int out_size) {
    const float* x1    = (const float*)d_in[0];
    const float* x2    = (const float*)d_in[1];
    const float* Wq    = (const float*)d_in[2];
    const float* bq    = (const float*)d_in[3];
    const float* Wk    = (const float*)d_in[4];
    const float* bk    = (const float*)d_in[5];
    const float* Wv    = (const float*)d_in[6];
    const float* Wsc   = (const float*)d_in[7];
    const float* gamma = (const float*)d_in[8];
    float* out = (float*)d_out;

    const int smemA = 2 * 16 * QST * 4;       // 66560
    const int smemB = 18688 * 4;              // 74752
    cudaFuncSetAttribute(kA_stats, cudaFuncAttributeMaxDynamicSharedMemorySize, smemA);
    cudaFuncSetAttribute(kB_out,   cudaFuncAttributeMaxDynamicSharedMemorySize, smemB);

    k0_wu<<<8, 256>>>(Wsc, Wv);
    dim3 g1(HW / 64, BATCH);
    k1_proj<<<g1, 256>>>(x1, x2, Wq, bq, Wk, bk, Wsc);
    dim3 g2(HW / 64, BATCH);
    kA_stats<<<g2, 512, smemA>>>(gamma);
    kW<<<2048, 256>>>();
    dim3 g3(HW / 64, BATCH);
    kB_out<<<g3, 512, smemB>>>(out);
}